// round 1
// baseline (speedup 1.0000x reference)
#include <cuda_runtime.h>
#include <cstdint>

// ---------------------------------------------------------------------------
// Problem constants
// ---------------------------------------------------------------------------
#define BATCH 512
#define TSEQ  64
#define P_DIM 8
#define Q_DIM 24
#define N_DIM 32
#define PQ    (P_DIM * Q_DIM)   // 192

// Scratch (no cudaMalloc allowed)
__device__ float g_yb[N_DIM * N_DIM];            // bias Cayley rotation, 32x32
__device__ float g_U[2 * BATCH * N_DIM * P_DIM]; // 1024 x (32x8) panels

// ---------------------------------------------------------------------------
// Kernel 1: yb = cayley(tangent(question_bias)), bias is O(1) so do a real
// 8x8 Gauss-Jordan inverse (SPD, I + b b^T, pivots >= 1, no pivoting needed).
// ---------------------------------------------------------------------------
__global__ __launch_bounds__(256) void yb_kernel(const float* __restrict__ bias)
{
    __shared__ float sb[PQ];        // b, 8x24
    __shared__ float sA[8 * 16];    // augmented [I + b b^T | I]
    __shared__ float sW[PQ];        // W = K b
    __shared__ float spiv;

    const int tid = threadIdx.x;

    if (tid < PQ) sb[tid] = bias[tid];
    __syncthreads();

    if (tid < 64) {
        int i = tid >> 3, j = tid & 7;
        float g = (i == j) ? 1.0f : 0.0f;
        #pragma unroll
        for (int k = 0; k < Q_DIM; ++k) g += sb[i * Q_DIM + k] * sb[j * Q_DIM + k];
        sA[i * 16 + j]     = g;
        sA[i * 16 + 8 + j] = (i == j) ? 1.0f : 0.0f;
    }
    __syncthreads();

    // Gauss-Jordan
    for (int k = 0; k < 8; ++k) {
        if (tid == 0) spiv = 1.0f / sA[k * 16 + k];
        __syncthreads();
        float newv = 0.0f;
        int i = tid >> 4, c = tid & 15;
        if (tid < 128) {
            float akc = sA[k * 16 + c] * spiv;   // normalized pivot row
            float aik = sA[i * 16 + k];
            newv = (i == k) ? akc : (sA[i * 16 + c] - aik * akc);
        }
        __syncthreads();
        if (tid < 128) sA[i * 16 + c] = newv;
        __syncthreads();
    }

    // W = K b  (K = right half of sA)
    if (tid < PQ) {
        int i = tid / Q_DIM, j = tid % Q_DIM;
        float w = 0.0f;
        #pragma unroll
        for (int k = 0; k < 8; ++k) w += sA[i * 16 + 8 + k] * sb[k * Q_DIM + j];
        sW[tid] = w;
    }
    __syncthreads();

    // Y = [[2K - I, -2W], [2W^T, I - 2 b^T W]]
    #pragma unroll
    for (int e = 0; e < 4; ++e) {
        int idx = tid + 256 * e;
        int r = idx >> 5, c = idx & 31;
        float y;
        if (r < 8 && c < 8) {
            y = 2.0f * sA[r * 16 + 8 + c] - ((r == c) ? 1.0f : 0.0f);
        } else if (r < 8) {
            y = -2.0f * sW[r * Q_DIM + (c - 8)];
        } else if (c < 8) {
            y = 2.0f * sW[c * Q_DIM + (r - 8)];
        } else {
            int j = r - 8, cc = c - 8;
            float acc = 0.0f;
            #pragma unroll
            for (int i = 0; i < 8; ++i) acc += sb[i * Q_DIM + j] * sW[i * Q_DIM + cc];
            y = ((j == cc) ? 1.0f : 0.0f) - 2.0f * acc;
        }
        g_yb[idx] = y;
    }
}

// ---------------------------------------------------------------------------
// Kernel 2: per-sequence chain. One block per (batch, q/a) pair.
// Propagates C = Z[:, :8] right-to-left:  C <- Y_t C for t = 63..0.
// Structured update (W = (I+xx^T)^{-1} x via 2-term Neumann):
//   S  = x^T C1 + C2                 (24x8)
//   V  = W C2                        (8x8)
//   C1 <- C1 - 2 W S
//   C2 <- C2 + 2 (W^T C1 - x^T V)
// ---------------------------------------------------------------------------
__global__ __launch_bounds__(256) void seq_kernel(
    const int*   __restrict__ sent_q,
    const int*   __restrict__ sent_a,
    const float* __restrict__ emb_q,
    const float* __restrict__ emb_a,
    const float* __restrict__ transforms)
{
    const int bid  = blockIdx.x;
    const bool is_q = (bid < BATCH);
    const int b    = is_q ? bid : (bid - BATCH);
    const int* sent       = is_q ? sent_q : sent_a;
    const float* emb      = is_q ? emb_q  : emb_a;
    const int tid = threadIdx.x;

    __shared__ float sx[PQ];        // x (8x24), row-major
    __shared__ float sG[64];        // x x^T
    __shared__ float sK[64];        // I - G + G^2
    __shared__ float sW[PQ];        // K x
    __shared__ float sS[Q_DIM * 8]; // x^T C1 + C2
    __shared__ float sV[64];        // W C2
    __shared__ float sC[N_DIM * 8]; // 32x8 panel, sC[r*8+c]
    __shared__ int   stok[TSEQ];

    float tf = 1.0f;
    if (is_q && tid < PQ) tf = transforms[tid];

    if (tid < TSEQ) stok[tid] = sent[b * TSEQ + tid];
    // C = [I8; 0]
    {
        int r = tid >> 3, c = tid & 7;
        sC[tid] = (r == c) ? 1.0f : 0.0f;
    }
    __syncthreads();

    if (tid < PQ) sx[tid] = emb[(size_t)stok[TSEQ - 1] * PQ + tid] * tf;
    __syncthreads();

    for (int t = TSEQ - 1; t >= 0; --t) {
        // prefetch next token's embedding row (hides ~L2 latency under math)
        float xn = 0.0f;
        if (t > 0 && tid < PQ) xn = emb[(size_t)stok[t - 1] * PQ + tid];

        // ---- Phase A: G = x x^T (64 thr)  |  S = x^T C1 + C2 (192 thr)
        if (tid < 64) {
            int i = tid >> 3, j = tid & 7;
            float g = 0.0f;
            #pragma unroll
            for (int k = 0; k < Q_DIM; ++k) g += sx[i * Q_DIM + k] * sx[j * Q_DIM + k];
            sG[tid] = g;
        } else {
            int u = tid - 64;
            int j = u >> 3, c = u & 7;
            float s = sC[(8 + j) * 8 + c];
            #pragma unroll
            for (int i = 0; i < 8; ++i) s += sx[i * Q_DIM + j] * sC[i * 8 + c];
            sS[u] = s;
        }
        __syncthreads();

        // ---- Phase B: K = I - G + G^2   (||G|| ~ 5e-4 -> err ~1e-10)
        if (tid < 64) {
            int i = tid >> 3, j = tid & 7;
            float k = ((i == j) ? 1.0f : 0.0f) - sG[tid];
            #pragma unroll
            for (int m = 0; m < 8; ++m) k += sG[i * 8 + m] * sG[m * 8 + j];
            sK[tid] = k;
        }
        __syncthreads();

        // ---- Phase C: W = K x (192 thr)
        if (tid < PQ) {
            int i = tid / Q_DIM, j = tid % Q_DIM;
            float w = 0.0f;
            #pragma unroll
            for (int k = 0; k < 8; ++k) w += sK[i * 8 + k] * sx[k * Q_DIM + j];
            sW[tid] = w;
        }
        __syncthreads();

        // ---- Phase D: V = W C2 (64 thr)
        if (tid < 64) {
            int i = tid >> 3, c = tid & 7;
            float v = 0.0f;
            #pragma unroll
            for (int j = 0; j < Q_DIM; ++j) v += sW[i * Q_DIM + j] * sC[(8 + j) * 8 + c];
            sV[tid] = v;
        }
        __syncthreads();

        // ---- Phase E: new C into registers
        float nc;
        if (tid < 64) {
            int i = tid >> 3, c = tid & 7;
            float acc = 0.0f;
            #pragma unroll
            for (int j = 0; j < Q_DIM; ++j) acc += sW[i * Q_DIM + j] * sS[j * 8 + c];
            nc = sC[i * 8 + c] - 2.0f * acc;
        } else {
            int u = tid - 64;
            int j = u >> 3, c = u & 7;
            float acc = 0.0f;
            #pragma unroll
            for (int i = 0; i < 8; ++i)
                acc += sW[i * Q_DIM + j] * sC[i * 8 + c] - sx[i * Q_DIM + j] * sV[i * 8 + c];
            nc = sC[(8 + j) * 8 + c] + 2.0f * acc;
        }
        __syncthreads();

        // ---- Commit: C update + next x
        sC[tid] = nc;
        if (t > 0 && tid < PQ) sx[tid] = xn * tf;
        __syncthreads();
    }

    // Final panel: question gets the bias rotation, answer is raw.
    float u;
    {
        int r = tid >> 3, c = tid & 7;
        if (is_q) {
            float acc = 0.0f;
            #pragma unroll
            for (int k = 0; k < N_DIM; ++k) acc += g_yb[r * N_DIM + k] * sC[k * 8 + c];
            u = acc;
        } else {
            u = sC[tid];
        }
    }
    g_U[(size_t)bid * (N_DIM * P_DIM) + tid] = u;
}

// ---------------------------------------------------------------------------
// Kernel 3: dist_b = || U1 U1^T - U2 U2^T ||_F ; out = -wf*dist + wb
// ---------------------------------------------------------------------------
__global__ __launch_bounds__(256) void dist_kernel(
    const float* __restrict__ wf,
    const float* __restrict__ wb,
    float* __restrict__ out)
{
    const int b = blockIdx.x;
    const int tid = threadIdx.x;
    __shared__ float U1[N_DIM * 8];
    __shared__ float U2[N_DIM * 8];
    __shared__ float warpsum[8];

    U1[tid] = g_U[(size_t)b * 256 + tid];
    U2[tid] = g_U[(size_t)(BATCH + b) * 256 + tid];
    __syncthreads();

    float acc = 0.0f;
    #pragma unroll
    for (int e = 0; e < 4; ++e) {
        int idx = tid + 256 * e;
        int i = idx >> 5, j = idx & 31;
        float d = 0.0f;
        #pragma unroll
        for (int c = 0; c < 8; ++c)
            d += U1[i * 8 + c] * U1[j * 8 + c] - U2[i * 8 + c] * U2[j * 8 + c];
        acc += d * d;
    }

    #pragma unroll
    for (int off = 16; off > 0; off >>= 1)
        acc += __shfl_xor_sync(0xFFFFFFFFu, acc, off);
    if ((tid & 31) == 0) warpsum[tid >> 5] = acc;
    __syncthreads();
    if (tid == 0) {
        float s = 0.0f;
        #pragma unroll
        for (int w = 0; w < 8; ++w) s += warpsum[w];
        out[b] = -(*wf) * sqrtf(s) + (*wb);
    }
}

// ---------------------------------------------------------------------------
extern "C" void kernel_launch(void* const* d_in, const int* in_sizes, int n_in,
                              void* d_out, int out_size)
{
    const int*   s1 = (const int*)  d_in[0];   // sentence_1 [512,64]
    const int*   s2 = (const int*)  d_in[1];   // sentence_2 [512,64]
    const float* qe = (const float*)d_in[2];   // question_embedding [32000,8,24]
    const float* ae = (const float*)d_in[3];   // answer_embedding   [32000,8,24]
    const float* qt = (const float*)d_in[4];   // question_transforms [8,24]
    const float* qb = (const float*)d_in[5];   // question_bias [8,24]
    const float* wf = (const float*)d_in[6];
    const float* wb = (const float*)d_in[7];
    float* out = (float*)d_out;

    yb_kernel<<<1, 256>>>(qb);
    seq_kernel<<<2 * BATCH, 256>>>(s1, s2, qe, ae, qt);
    dist_kernel<<<BATCH, 256>>>(wf, wb, out);
}